// round 1
// baseline (speedup 1.0000x reference)
#include <cuda_runtime.h>
#include <cstdint>

// Problem constants
#define B_SZ 512
#define D_SZ 256
#define C_SZ 100000
#define MARGIN 0.2f
#define SCALE  30.0f

// GEMM tiling
#define BM 128
#define BN 64
#define BK 32
#define NCHUNK ((C_SZ + BN - 1) / BN)   // 1563

// Scratch (device globals: no allocations allowed)
__device__ float g_xn[B_SZ * D_SZ];        // normalized x
__device__ float g_winv[C_SZ];             // 1/max(||w_c||, eps)
__device__ float g_pmax[B_SZ * NCHUNK];    // per-(b, cChunk) partial max
__device__ float g_psum[B_SZ * NCHUNK];    // per-(b, cChunk) partial sumexp
__device__ float g_logZ[B_SZ];
__device__ float g_v[B_SZ * 4];            // out[b, {t1,p1,t2,p2}] after scatter semantics

// ---------- packed f32x2 helpers (sm_100+ PTX) ----------
__device__ __forceinline__ unsigned long long splat2(float a) {
    unsigned long long r;
    asm("mov.b64 %0, {%1, %1};" : "=l"(r) : "f"(a));
    return r;
}
__device__ __forceinline__ void fma2(unsigned long long& acc,
                                     unsigned long long a,
                                     unsigned long long b) {
    asm("fma.rn.f32x2 %0, %1, %2, %0;" : "+l"(acc) : "l"(a), "l"(b));
}
__device__ __forceinline__ float lo32(unsigned long long v) {
    return __uint_as_float((unsigned)(v & 0xffffffffull));
}
__device__ __forceinline__ float hi32(unsigned long long v) {
    return __uint_as_float((unsigned)(v >> 32));
}

// ---------- kernel 1: normalize x (inputs [B, D, 1]) ----------
__global__ void xnorm_kernel(const float* __restrict__ x) {
    int b = blockIdx.x;
    int t = threadIdx.x;            // 256 threads, one per d
    float v = x[b * D_SZ + t];
    float s = v * v;
    #pragma unroll
    for (int m = 16; m; m >>= 1) s += __shfl_xor_sync(0xffffffffu, s, m);
    __shared__ float ws[8];
    if ((t & 31) == 0) ws[t >> 5] = s;
    __syncthreads();
    __shared__ float inv;
    if (t == 0) {
        float tot = 0.f;
        #pragma unroll
        for (int i = 0; i < 8; i++) tot += ws[i];
        inv = 1.0f / fmaxf(sqrtf(tot), 1e-12f);
    }
    __syncthreads();
    g_xn[b * D_SZ + t] = v * inv;
}

// ---------- kernel 2: per-class inverse weight norms ----------
__global__ void wnorm_kernel(const float* __restrict__ w) {
    int warp = (blockIdx.x * blockDim.x + threadIdx.x) >> 5;
    int lane = threadIdx.x & 31;
    if (warp >= C_SZ) return;
    const float4* wr = (const float4*)(w + (size_t)warp * D_SZ);
    float4 a = wr[lane];
    float4 b = wr[lane + 32];
    float s = a.x * a.x + a.y * a.y + a.z * a.z + a.w * a.w
            + b.x * b.x + b.y * b.y + b.z * b.z + b.w * b.w;
    #pragma unroll
    for (int m = 16; m; m >>= 1) s += __shfl_xor_sync(0xffffffffu, s, m);
    if (lane == 0) g_winv[warp] = 1.0f / fmaxf(sqrtf(s), 1e-12f);
}

// ---------- kernel 3: fused GEMM (x_norm @ w^T) + penalty scatter + partial LSE ----------
// grid (NCHUNK, 4), 256 threads. Thread tile 8(m) x 4(n), f32x2-packed over m.
__global__ void __launch_bounds__(256)
gemm_lse_kernel(const float* __restrict__ w,
                const int* __restrict__ t1, const int* __restrict__ p1,
                const int* __restrict__ t2, const int* __restrict__ p2) {
    __shared__ __align__(16) float As[BK][BM];   // 16 KB, transposed x tile
    __shared__ __align__(16) float Bs[BK][BN];   // 8 KB,  transposed w tile
    __shared__ int sIdx[4][BM];                  // 2 KB, per-row scatter indices

    const int cChunk = blockIdx.x;
    const int b0 = blockIdx.y * BM;
    const int c0 = cChunk * BN;
    const int tid = threadIdx.x;
    const int ty = tid >> 4;         // 0..15 -> m group
    const int tx = tid & 15;         // 0..15 -> n group

    for (int i = tid; i < BM; i += 256) {
        int b = b0 + i;
        sIdx[0][i] = t1[b]; sIdx[1][i] = p1[b];
        sIdx[2][i] = t2[b]; sIdx[3][i] = p2[b];
    }

    unsigned long long acc[4][4];    // [m-pair][n], each = {m=2i, m=2i+1}
    #pragma unroll
    for (int i = 0; i < 4; i++)
        #pragma unroll
        for (int j = 0; j < 4; j++) acc[i][j] = 0ull;

    for (int kt = 0; kt < D_SZ; kt += BK) {
        // load A tile: 128x32 floats (1024 float4), 4 per thread
        #pragma unroll
        for (int it = 0; it < 4; it++) {
            int pos = tid + it * 256;
            int r = pos >> 3, q = pos & 7;
            float4 v = *(const float4*)(g_xn + (size_t)(b0 + r) * D_SZ + kt + q * 4);
            As[q * 4 + 0][r] = v.x; As[q * 4 + 1][r] = v.y;
            As[q * 4 + 2][r] = v.z; As[q * 4 + 3][r] = v.w;
        }
        // load B tile: 64x32 floats (512 float4), 2 per thread; zero-fill OOB classes
        #pragma unroll
        for (int it = 0; it < 2; it++) {
            int pos = tid + it * 256;
            int r = pos >> 3, q = pos & 7;
            int c = c0 + r;
            float4 v = make_float4(0.f, 0.f, 0.f, 0.f);
            if (c < C_SZ) v = *(const float4*)(w + (size_t)c * D_SZ + kt + q * 4);
            Bs[q * 4 + 0][r] = v.x; Bs[q * 4 + 1][r] = v.y;
            Bs[q * 4 + 2][r] = v.z; Bs[q * 4 + 3][r] = v.w;
        }
        __syncthreads();

        #pragma unroll
        for (int kk = 0; kk < BK; kk++) {
            const ulonglong2* ap = (const ulonglong2*)&As[kk][ty * 8];
            ulonglong2 A0 = ap[0];
            ulonglong2 A1 = ap[1];
            unsigned long long am[4] = {A0.x, A0.y, A1.x, A1.y};
            float4 bf = *(const float4*)&Bs[kk][tx * 4];
            unsigned long long bs0 = splat2(bf.x), bs1 = splat2(bf.y);
            unsigned long long bs2 = splat2(bf.z), bs3 = splat2(bf.w);
            #pragma unroll
            for (int ip = 0; ip < 4; ip++) {
                fma2(acc[ip][0], am[ip], bs0);
                fma2(acc[ip][1], am[ip], bs1);
                fma2(acc[ip][2], am[ip], bs2);
                fma2(acc[ip][3], am[ip], bs3);
            }
        }
        __syncthreads();
    }

    // Epilogue: penalty cascade + per-row (max, sumexp) over this 64-class chunk.
    // Row b's 64 classes live on the 16 threads sharing ty (a half-warp:
    // lane = (ty&1)*16 + tx, so xor-shuffles with masks 1,2,4,8 stay in-group).
    #pragma unroll
    for (int ip = 0; ip < 4; ip++) {
        #pragma unroll
        for (int half = 0; half < 2; half++) {
            int i = ip * 2 + half;
            int bl = ty * 8 + i;
            int b = b0 + bl;
            int i0 = sIdx[0][bl], i1 = sIdx[1][bl], i2 = sIdx[2][bl], i3 = sIdx[3][bl];
            float v[4];
            float rmax = -1e30f;
            #pragma unroll
            for (int j = 0; j < 4; j++) {
                int c = c0 + tx * 4 + j;
                float val = -1e30f;
                if (c < C_SZ) {
                    float accf = half ? hi32(acc[ip][j]) : lo32(acc[ip][j]);
                    float cosv = accf * g_winv[c];
                    val = SCALE * cosv;
                    if (c == i0) val = SCALE * (cosv - MARGIN);  // scattered pre-scale
                    if (c == i1) val = cosv - MARGIN;            // scattered post-scale
                    if (c == i2) val = cosv - MARGIN;
                    if (c == i3) val = cosv - MARGIN;            // last write wins
                }
                v[j] = val;
                rmax = fmaxf(rmax, val);
            }
            #pragma unroll
            for (int m = 8; m >= 1; m >>= 1)
                rmax = fmaxf(rmax, __shfl_xor_sync(0xffffffffu, rmax, m));
            float se = __expf(v[0] - rmax) + __expf(v[1] - rmax)
                     + __expf(v[2] - rmax) + __expf(v[3] - rmax);
            #pragma unroll
            for (int m = 8; m >= 1; m >>= 1)
                se += __shfl_xor_sync(0xffffffffu, se, m);
            if (tx == 0) {
                g_pmax[(size_t)b * NCHUNK + cChunk] = rmax;
                g_psum[(size_t)b * NCHUNK + cChunk] = se;
            }
        }
    }
}

// ---------- kernel 4: merge partials -> logZ[b] ----------
__global__ void lse_reduce_kernel() {
    int b = blockIdx.x;
    int t = threadIdx.x;     // 256
    float m = -1e30f, s = 0.f;
    for (int i = t; i < NCHUNK; i += 256) {
        float mi = g_pmax[(size_t)b * NCHUNK + i];
        float si = g_psum[(size_t)b * NCHUNK + i];
        float nm = fmaxf(m, mi);
        s = s * __expf(m - nm) + si * __expf(mi - nm);
        m = nm;
    }
    __shared__ float sm[256], ss[256];
    sm[t] = m; ss[t] = s;
    __syncthreads();
    for (int st = 128; st; st >>= 1) {
        if (t < st) {
            float m2 = sm[t + st], s2 = ss[t + st];
            float nm = fmaxf(sm[t], m2);
            ss[t] = ss[t] * __expf(sm[t] - nm) + s2 * __expf(m2 - nm);
            sm[t] = nm;
        }
        __syncthreads();
    }
    if (t == 0) g_logZ[b] = sm[0] + logf(ss[0]);
}

// ---------- kernel 5: the 4 gathered logits per row (post-scatter values) ----------
__global__ void specials_kernel(const float* __restrict__ w,
                                const int* __restrict__ t1, const int* __restrict__ p1,
                                const int* __restrict__ t2, const int* __restrict__ p2) {
    int b = blockIdx.x;
    int q = threadIdx.x >> 5;        // 4 warps, one per query
    int lane = threadIdx.x & 31;
    int i0 = t1[b], i1 = p1[b], i2 = t2[b], i3 = p2[b];
    int qi = (q == 0) ? i0 : (q == 1) ? i1 : (q == 2) ? i2 : i3;
    const float* wr = w + (size_t)qi * D_SZ;
    const float* xr = g_xn + (size_t)b * D_SZ;
    float s = 0.f;
    #pragma unroll
    for (int it = 0; it < 8; it++) {
        int d = lane + it * 32;
        s += xr[d] * wr[d];
    }
    #pragma unroll
    for (int m = 16; m; m >>= 1) s += __shfl_xor_sync(0xffffffffu, s, m);
    if (lane == 0) {
        float cosv = s * g_winv[qi];
        float val = SCALE * cosv;
        if (qi == i0) val = SCALE * (cosv - MARGIN);
        if (qi == i1) val = cosv - MARGIN;
        if (qi == i2) val = cosv - MARGIN;
        if (qi == i3) val = cosv - MARGIN;
        g_v[b * 4 + q] = val;
    }
}

// ---------- kernel 6: final mixed CE scalar ----------
__global__ void final_kernel(const float* __restrict__ lamp, float* __restrict__ out) {
    int b = threadIdx.x;             // 512
    float lam = *lamp;
    float lz = g_logZ[b];
    float l = lam * (0.2f * (lz - g_v[b * 4 + 0]) + 0.8f * (lz - g_v[b * 4 + 1]))
            + (1.f - lam) * (0.2f * (lz - g_v[b * 4 + 2]) + 0.8f * (lz - g_v[b * 4 + 3]));
    __shared__ float red[512];
    red[b] = l;
    __syncthreads();
    for (int st = 256; st; st >>= 1) {
        if (b < st) red[b] += red[b + st];
        __syncthreads();
    }
    if (b == 0) out[0] = red[0] / (float)B_SZ;
}

// ---------- launch ----------
extern "C" void kernel_launch(void* const* d_in, const int* in_sizes, int n_in,
                              void* d_out, int out_size) {
    const float* x   = (const float*)d_in[0];   // [512, 256, 1]
    const float* w   = (const float*)d_in[1];   // [100000, 256]
    const float* lam = (const float*)d_in[2];   // scalar
    const int* t1    = (const int*)d_in[3];
    const int* p1    = (const int*)d_in[4];
    const int* t2    = (const int*)d_in[5];
    const int* p2    = (const int*)d_in[6];
    float* out = (float*)d_out;

    xnorm_kernel<<<B_SZ, 256>>>(x);
    wnorm_kernel<<<(C_SZ + 7) / 8, 256>>>(w);
    gemm_lse_kernel<<<dim3(NCHUNK, B_SZ / BM), 256>>>(w, t1, p1, t2, p2);
    lse_reduce_kernel<<<B_SZ, 256>>>();
    specials_kernel<<<B_SZ, 128>>>(w, t1, p1, t2, p2);
    final_kernel<<<1, 512>>>(lam, out);
}

// round 3
// speedup vs baseline: 6.9570x; 6.9570x over previous
#include <cuda_runtime.h>
#include <cuda_bf16.h>
#include <cstdint>

// ---------------- problem constants ----------------
#define B_SZ 512
#define D_SZ 256
#define C_SZ 100000
#define C_PAD 100096              // 782 * 128
#define NCHB 782                  // class chunks of 128
#define MARGIN 0.2f
#define SCALE  30.0f
#define SHIFT  30.0f              // fixed LSE shift: logits <= S = 30

// GEMM smem: 4 stages x (A 8KB + B 8KB) = 64KB, + 2KB reduce buffer
#define STAGE_BYTES 16384
#define RBUF_OFF    65536
#define GEMM_SMEM   (65536 + 2048)

// ---------------- device scratch (no runtime alloc) ----------------
__device__ __align__(16) __nv_bfloat16 g_wbf[(size_t)C_PAD * D_SZ]; // l2norm(W) bf16; pad rows zero
__device__ __align__(16) __nv_bfloat16 g_xbf[B_SZ * D_SZ];          // S * l2norm(x) bf16
__device__ float g_psum[(size_t)B_SZ * NCHB];   // per-(row, chunk) sum of exp(v - SHIFT)
__device__ float g_logZ[B_SZ];
__device__ float g_v[B_SZ * 4];     // post-scatter values at special indices
__device__ float g_vraw[B_SZ * 4];  // raw S*cos at special indices

// ---------------- PTX helpers ----------------
__device__ __forceinline__ uint32_t smem_u32(const void* p) {
    uint32_t a;
    asm("{ .reg .u64 t; cvta.to.shared.u64 t, %1; cvt.u32.u64 %0, t; }" : "=r"(a) : "l"(p));
    return a;
}
#define CP_ASYNC16(dst, src) \
    asm volatile("cp.async.cg.shared.global [%0], [%1], 16;" :: "r"(dst), "l"(src) : "memory")
#define CP_COMMIT() asm volatile("cp.async.commit_group;" ::: "memory")
#define CP_WAIT(n)  asm volatile("cp.async.wait_group %0;" :: "n"(n) : "memory")

#define LDSM_X4(r0, r1, r2, r3, addr) \
    asm volatile("ldmatrix.sync.aligned.m8n8.x4.shared.b16 {%0,%1,%2,%3}, [%4];" \
        : "=r"(r0), "=r"(r1), "=r"(r2), "=r"(r3) : "r"(addr))

#define MMA_BF16(d0, d1, d2, d3, a0, a1, a2, a3, b0, b1) \
    asm volatile("mma.sync.aligned.m16n8k16.row.col.f32.bf16.bf16.f32 " \
        "{%0,%1,%2,%3}, {%4,%5,%6,%7}, {%8,%9}, {%0,%1,%2,%3};" \
        : "+f"(d0), "+f"(d1), "+f"(d2), "+f"(d3) \
        : "r"(a0), "r"(a1), "r"(a2), "r"(a3), "r"(b0), "r"(b1))

// ---------------- kernel 1: x -> S * l2norm(x) in bf16 ----------------
__global__ void xnorm_kernel(const float* __restrict__ x) {
    int b = blockIdx.x, t = threadIdx.x;          // 256 threads
    float v = x[b * D_SZ + t];
    float s = v * v;
    #pragma unroll
    for (int m = 16; m; m >>= 1) s += __shfl_xor_sync(0xffffffffu, s, m);
    __shared__ float ws[8];
    if ((t & 31) == 0) ws[t >> 5] = s;
    __syncthreads();
    __shared__ float inv;
    if (t == 0) {
        float tot = 0.f;
        #pragma unroll
        for (int i = 0; i < 8; i++) tot += ws[i];
        inv = 1.0f / fmaxf(sqrtf(tot), 1e-12f);
    }
    __syncthreads();
    g_xbf[b * D_SZ + t] = __float2bfloat16(SCALE * v * inv);
}

// ---------------- kernel 2: W -> l2norm(W) in bf16 (pad rows stay zero) ----------------
__global__ void wconv_kernel(const float* __restrict__ w) {
    int warp = (blockIdx.x * blockDim.x + threadIdx.x) >> 5;
    int lane = threadIdx.x & 31;
    if (warp >= C_SZ) return;
    const float4* wr = (const float4*)(w + (size_t)warp * D_SZ);
    float4 a = wr[lane];
    float4 b = wr[lane + 32];
    float s = a.x*a.x + a.y*a.y + a.z*a.z + a.w*a.w
            + b.x*b.x + b.y*b.y + b.z*b.z + b.w*b.w;
    #pragma unroll
    for (int m = 16; m; m >>= 1) s += __shfl_xor_sync(0xffffffffu, s, m);
    float inv = 1.0f / fmaxf(sqrtf(s), 1e-12f);
    __nv_bfloat162* out = (__nv_bfloat162*)(g_wbf + (size_t)warp * D_SZ);
    __nv_bfloat162 p0, p1, q0, q1;
    p0.x = __float2bfloat16(a.x * inv); p0.y = __float2bfloat16(a.y * inv);
    p1.x = __float2bfloat16(a.z * inv); p1.y = __float2bfloat16(a.w * inv);
    q0.x = __float2bfloat16(b.x * inv); q0.y = __float2bfloat16(b.y * inv);
    q1.x = __float2bfloat16(b.z * inv); q1.y = __float2bfloat16(b.w * inv);
    out[2 * lane]      = p0;
    out[2 * lane + 1]  = p1;
    out[64 + 2 * lane]     = q0;
    out[64 + 2 * lane + 1] = q1;
}

// ---------------- kernel 3: HMMA GEMM + exp-sum epilogue ----------------
// grid (782, 4): 128 classes x 128 batch rows per CTA. 256 threads = 8 warps (2m x 4n),
// each warp 64m x 32n via m16n8k16. cp.async 4-stage pipeline, BK=32.
__global__ void __launch_bounds__(256, 2)
gemm_lse_kernel() {
    extern __shared__ __align__(1024) char smem[];
    const uint32_t sb = smem_u32(smem);
    const int tid = threadIdx.x, lane = tid & 31, wid = tid >> 5;
    const int wm = wid >> 2, wn = wid & 3;            // warp grid 2 x 4
    const int chunk = blockIdx.x, c0 = chunk * 128, b0 = blockIdx.y * 128;

    // ---- cp.async producer indexing (swizzled 16B chunks) ----
    const int ldRow = tid >> 2, ldC16 = tid & 3;
    const uint32_t swzOff = (uint32_t)ldRow * 64 +
                            ((uint32_t)(ldC16 ^ ((ldRow >> 1) & 3)) << 4);
    const __nv_bfloat16* gA = g_xbf + (size_t)(b0 + ldRow) * D_SZ + ldC16 * 8;
    const __nv_bfloat16* gB = g_wbf + (size_t)(c0 + ldRow) * D_SZ + ldC16 * 8;

    auto load_stage = [&](int kt) {
        uint32_t abase = sb + (kt & 3) * STAGE_BYTES;
        uint32_t bbase = abase + 8192;
        const __nv_bfloat16* a = gA + kt * 32;
        const __nv_bfloat16* b = gB + kt * 32;
        CP_ASYNC16(abase + swzOff,        a);
        CP_ASYNC16(abase + swzOff + 4096, a + (size_t)64 * D_SZ);
        CP_ASYNC16(bbase + swzOff,        b);
        CP_ASYNC16(bbase + swzOff + 4096, b + (size_t)64 * D_SZ);
    };

    // ---- ldmatrix consumer indexing ----
    const int rA = wm * 64 + (lane & 15);             // A row for this lane
    const uint32_t aoff = (uint32_t)rA * 64;
    const int saN = (rA >> 1) & 3;
    const int cA = lane >> 4;                         // + s*2
    const int rB = wn * 32 + ((lane >> 4) << 3) + (lane & 7);
    const uint32_t boff = (uint32_t)rB * 64;
    const int sbN = (rB >> 1) & 3;
    const int cB = (lane >> 3) & 1;                   // + s*2

    float acc[4][4][4];
    #pragma unroll
    for (int i = 0; i < 4; i++)
        #pragma unroll
        for (int j = 0; j < 4; j++)
            #pragma unroll
            for (int e = 0; e < 4; e++) acc[i][j][e] = 0.f;

    auto compute_stage = [&](int st) {
        uint32_t aBase = sb + st * STAGE_BYTES;
        uint32_t bBase = aBase + 8192;
        #pragma unroll
        for (int s = 0; s < 2; s++) {                 // two k16 steps per BK=32
            uint32_t a_[4][4], b_[2][4];
            #pragma unroll
            for (int mt = 0; mt < 4; mt++) {
                uint32_t ad = aBase + aoff + mt * 1024 +
                              ((uint32_t)((s * 2 + cA) ^ saN) << 4);
                LDSM_X4(a_[mt][0], a_[mt][1], a_[mt][2], a_[mt][3], ad);
            }
            #pragma unroll
            for (int jp = 0; jp < 2; jp++) {
                uint32_t bd = bBase + boff + jp * 1024 +
                              ((uint32_t)((s * 2 + cB) ^ sbN) << 4);
                LDSM_X4(b_[jp][0], b_[jp][1], b_[jp][2], b_[jp][3], bd);
            }
            #pragma unroll
            for (int mt = 0; mt < 4; mt++)
                #pragma unroll
                for (int nt = 0; nt < 4; nt++) {
                    int jp = nt >> 1, hb = (nt & 1) * 2;
                    MMA_BF16(acc[mt][nt][0], acc[mt][nt][1], acc[mt][nt][2], acc[mt][nt][3],
                             a_[mt][0], a_[mt][1], a_[mt][2], a_[mt][3],
                             b_[jp][hb], b_[jp][hb + 1]);
                }
        }
    };

    // ---- pipeline: prime 3 stages, steady state keeps 3 in flight ----
    load_stage(0); CP_COMMIT();
    load_stage(1); CP_COMMIT();
    load_stage(2); CP_COMMIT();
    for (int kt = 0; kt < 6; kt++) {
        CP_WAIT(2); __syncthreads();
        compute_stage(kt & 3);
        __syncthreads();
        load_stage(kt + 3); CP_COMMIT();
    }
    CP_WAIT(1); __syncthreads(); compute_stage(2);
    CP_WAIT(0); __syncthreads(); compute_stage(3);

    // ---- epilogue: sum of exp(v - SHIFT) per row ----
    const bool edge = (c0 + 128 > C_SZ);
    float es[4][2];
    #pragma unroll
    for (int mt = 0; mt < 4; mt++) { es[mt][0] = 0.f; es[mt][1] = 0.f; }
    #pragma unroll
    for (int mt = 0; mt < 4; mt++)
        #pragma unroll
        for (int nt = 0; nt < 4; nt++) {
            int cgb = c0 + wn * 32 + nt * 8 + (lane & 3) * 2;
            #pragma unroll
            for (int h = 0; h < 2; h++)
                #pragma unroll
                for (int e = 0; e < 2; e++) {
                    float t = __expf(acc[mt][nt][h * 2 + e] - SHIFT);
                    if (edge && (cgb + e >= C_SZ)) t = 0.f;
                    es[mt][h] += t;
                }
        }
    #pragma unroll
    for (int m = 1; m <= 2; m <<= 1)
        #pragma unroll
        for (int mt = 0; mt < 4; mt++) {
            es[mt][0] += __shfl_xor_sync(0xffffffffu, es[mt][0], m);
            es[mt][1] += __shfl_xor_sync(0xffffffffu, es[mt][1], m);
        }

    float* rbuf = (float*)(smem + RBUF_OFF);          // [2 wm][4 wn][64 rows]
    __syncthreads();                                  // done with stage smem reads
    if ((lane & 3) == 0) {
        int rl = lane >> 2;
        #pragma unroll
        for (int mt = 0; mt < 4; mt++) {
            rbuf[(wm * 4 + wn) * 64 + mt * 16 + rl]     = es[mt][0];
            rbuf[(wm * 4 + wn) * 64 + mt * 16 + 8 + rl] = es[mt][1];
        }
    }
    __syncthreads();
    if (tid < 128) {
        int wmx = tid >> 6, rl = tid & 63;
        float s = rbuf[(wmx * 4 + 0) * 64 + rl] + rbuf[(wmx * 4 + 1) * 64 + rl]
                + rbuf[(wmx * 4 + 2) * 64 + rl] + rbuf[(wmx * 4 + 3) * 64 + rl];
        g_psum[(size_t)(b0 + tid) * NCHB + chunk] = s;
    }
}

// ---------------- kernel 4: special entries (same bf16 operands as GEMM) ----------------
__global__ void specials_kernel(const int* __restrict__ t1, const int* __restrict__ p1,
                                const int* __restrict__ t2, const int* __restrict__ p2) {
    int b = blockIdx.x;
    int q = threadIdx.x >> 5, lane = threadIdx.x & 31;   // 4 warps
    int i0 = t1[b], i1 = p1[b], i2 = t2[b], i3 = p2[b];
    int qi = (q == 0) ? i0 : (q == 1) ? i1 : (q == 2) ? i2 : i3;
    const uint4* xr = (const uint4*)(g_xbf + (size_t)b * D_SZ);
    const uint4* wr = (const uint4*)(g_wbf + (size_t)qi * D_SZ);
    uint4 xv = xr[lane], wv = wr[lane];   // 8 bf16 each
    float s = 0.f;
    const uint32_t* xu = (const uint32_t*)&xv;
    const uint32_t* wu = (const uint32_t*)&wv;
    #pragma unroll
    for (int i = 0; i < 4; i++) {
        float2 xf = __bfloat1622float2(*(const __nv_bfloat162*)&xu[i]);
        float2 wf = __bfloat1622float2(*(const __nv_bfloat162*)&wu[i]);
        s += xf.x * wf.x + xf.y * wf.y;
    }
    #pragma unroll
    for (int m = 16; m; m >>= 1) s += __shfl_xor_sync(0xffffffffu, s, m);
    if (lane == 0) {
        float raw = s;                       // = S * cos (bf16-quantized operands)
        float val = raw;
        if (qi == i0) val = raw - SCALE * MARGIN;          // S*(cos - M), pre-scale scatter
        if (qi == i1) val = raw / SCALE - MARGIN;          // cos - M, post-scale
        if (qi == i2) val = raw / SCALE - MARGIN;
        if (qi == i3) val = raw / SCALE - MARGIN;          // last write wins
        g_vraw[b * 4 + q] = raw;
        g_v[b * 4 + q] = val;
    }
}

// ---------------- kernel 5: merge partial sums + scatter corrections -> logZ ----------------
__global__ void lse_corr_kernel(const int* __restrict__ t1, const int* __restrict__ p1,
                                const int* __restrict__ t2, const int* __restrict__ p2) {
    int b = blockIdx.x, t = threadIdx.x;     // 256 threads
    float s = 0.f;
    for (int i = t; i < NCHB; i += 256) s += g_psum[(size_t)b * NCHB + i];
    __shared__ float ss[256];
    ss[t] = s;
    __syncthreads();
    for (int st = 128; st; st >>= 1) {
        if (t < st) ss[t] += ss[t + st];
        __syncthreads();
    }
    if (t == 0) {
        float S0 = ss[0];
        int idx[4] = {t1[b], p1[b], t2[b], p2[b]};
        #pragma unroll
        for (int q = 0; q < 3; q++) {
            bool last = true;
            #pragma unroll
            for (int r = q + 1; r < 4; r++) if (idx[r] == idx[q]) last = false;
            if (last) S0 += __expf(g_v[b*4+q] - SHIFT) - __expf(g_vraw[b*4+q] - SHIFT);
        }
        S0 += __expf(g_v[b*4+3] - SHIFT) - __expf(g_vraw[b*4+3] - SHIFT);
        g_logZ[b] = SHIFT + logf(S0);
    }
}

// ---------------- kernel 6: final mixed CE ----------------
__global__ void final_kernel(const float* __restrict__ lamp, float* __restrict__ out) {
    int b = threadIdx.x;     // 512
    float lam = *lamp;
    float lz = g_logZ[b];
    float l = lam * (0.2f * (lz - g_v[b*4+0]) + 0.8f * (lz - g_v[b*4+1]))
            + (1.f - lam) * (0.2f * (lz - g_v[b*4+2]) + 0.8f * (lz - g_v[b*4+3]));
    __shared__ float red[512];
    red[b] = l;
    __syncthreads();
    for (int st = 256; st; st >>= 1) {
        if (b < st) red[b] += red[b + st];
        __syncthreads();
    }
    if (b == 0) out[0] = red[0] / (float)B_SZ;
}

// ---------------- host launch ----------------
extern "C" void kernel_launch(void* const* d_in, const int* in_sizes, int n_in,
                              void* d_out, int out_size) {
    const float* x   = (const float*)d_in[0];
    const float* w   = (const float*)d_in[1];
    const float* lam = (const float*)d_in[2];
    const int* t1    = (const int*)d_in[3];
    const int* p1    = (const int*)d_in[4];
    const int* t2    = (const int*)d_in[5];
    const int* p2    = (const int*)d_in[6];
    float* out = (float*)d_out;

    static bool attr_set = false;
    if (!attr_set) {
        cudaFuncSetAttribute(gemm_lse_kernel,
                             cudaFuncAttributeMaxDynamicSharedMemorySize, GEMM_SMEM);
        attr_set = true;
    }

    xnorm_kernel<<<B_SZ, 256>>>(x);
    wconv_kernel<<<(C_SZ + 7) / 8, 256>>>(w);
    gemm_lse_kernel<<<dim3(NCHB, B_SZ / 128), 256, GEMM_SMEM>>>();
    specials_kernel<<<B_SZ, 128>>>(t1, p1, t2, p2);
    lse_corr_kernel<<<B_SZ, 256>>>(t1, p1, t2, p2);
    final_kernel<<<1, 512>>>(lam, out);
}

// round 4
// speedup vs baseline: 6.9737x; 1.0024x over previous
#include <cuda_runtime.h>
#include <cuda_bf16.h>
#include <cstdint>

// ---------------- problem constants ----------------
#define B_SZ 512
#define D_SZ 256
#define C_SZ 100000
#define C_PAD 100096              // 782 * 128
#define NCHB 782                  // class chunks of 128
#define MARGIN 0.2f
#define SCALE  30.0f
#define SHIFT  30.0f              // fixed LSE shift: logits <= S = 30
#define WCONV_BLOCKS 12500        // 8 classes per block

// GEMM smem: 4 stages x (A 8KB + B 8KB) = 64KB, + 2KB reduce buffer
#define STAGE_BYTES 16384
#define RBUF_OFF    65536
#define GEMM_SMEM   (65536 + 2048)

// ---------------- device scratch (no runtime alloc) ----------------
__device__ __align__(16) __nv_bfloat16 g_wbf[(size_t)C_PAD * D_SZ]; // l2norm(W) bf16; pad rows zero
__device__ __align__(16) __nv_bfloat16 g_xbf[B_SZ * D_SZ];          // S * l2norm(x) bf16
__device__ float g_psum[(size_t)B_SZ * NCHB];   // per-(row, chunk) sum of exp(v - SHIFT)
__device__ float g_loss[B_SZ];                  // per-row mixed CE contribution

// ---------------- PTX helpers ----------------
__device__ __forceinline__ uint32_t smem_u32(const void* p) {
    uint32_t a;
    asm("{ .reg .u64 t; cvta.to.shared.u64 t, %1; cvt.u32.u64 %0, t; }" : "=r"(a) : "l"(p));
    return a;
}
#define CP_ASYNC16(dst, src) \
    asm volatile("cp.async.cg.shared.global [%0], [%1], 16;" :: "r"(dst), "l"(src) : "memory")
#define CP_COMMIT() asm volatile("cp.async.commit_group;" ::: "memory")
#define CP_WAIT(n)  asm volatile("cp.async.wait_group %0;" :: "n"(n) : "memory")

#define LDSM_X4(r0, r1, r2, r3, addr) \
    asm volatile("ldmatrix.sync.aligned.m8n8.x4.shared.b16 {%0,%1,%2,%3}, [%4];" \
        : "=r"(r0), "=r"(r1), "=r"(r2), "=r"(r3) : "r"(addr))

#define MMA_BF16(d0, d1, d2, d3, a0, a1, a2, a3, b0, b1) \
    asm volatile("mma.sync.aligned.m16n8k16.row.col.f32.bf16.bf16.f32 " \
        "{%0,%1,%2,%3}, {%4,%5,%6,%7}, {%8,%9}, {%0,%1,%2,%3};" \
        : "+f"(d0), "+f"(d1), "+f"(d2), "+f"(d3) \
        : "r"(a0), "r"(a1), "r"(a2), "r"(a3), "r"(b0), "r"(b1))

// ---------------- kernel 1: fused prep ----------------
// blocks [0, 12500): W rows -> l2norm bf16 (8 classes/block, warp per class)
// blocks [12500, 13012): x row (b = blk - 12500) -> S * l2norm(x) bf16
__global__ void prep_kernel(const float* __restrict__ w, const float* __restrict__ x) {
    if (blockIdx.x < WCONV_BLOCKS) {
        int cls = blockIdx.x * 8 + (threadIdx.x >> 5);
        int lane = threadIdx.x & 31;
        if (cls >= C_SZ) return;
        const float4* wr = (const float4*)(w + (size_t)cls * D_SZ);
        float4 a = wr[lane];
        float4 b = wr[lane + 32];
        float s = a.x*a.x + a.y*a.y + a.z*a.z + a.w*a.w
                + b.x*b.x + b.y*b.y + b.z*b.z + b.w*b.w;
        #pragma unroll
        for (int m = 16; m; m >>= 1) s += __shfl_xor_sync(0xffffffffu, s, m);
        float inv = 1.0f / fmaxf(sqrtf(s), 1e-12f);
        __nv_bfloat162* out = (__nv_bfloat162*)(g_wbf + (size_t)cls * D_SZ);
        __nv_bfloat162 p0, p1, q0, q1;
        p0.x = __float2bfloat16(a.x * inv); p0.y = __float2bfloat16(a.y * inv);
        p1.x = __float2bfloat16(a.z * inv); p1.y = __float2bfloat16(a.w * inv);
        q0.x = __float2bfloat16(b.x * inv); q0.y = __float2bfloat16(b.y * inv);
        q1.x = __float2bfloat16(b.z * inv); q1.y = __float2bfloat16(b.w * inv);
        out[2 * lane]          = p0;
        out[2 * lane + 1]      = p1;
        out[64 + 2 * lane]     = q0;
        out[64 + 2 * lane + 1] = q1;
    } else {
        int b = blockIdx.x - WCONV_BLOCKS, t = threadIdx.x;   // 256 threads
        float v = x[b * D_SZ + t];
        float s = v * v;
        #pragma unroll
        for (int m = 16; m; m >>= 1) s += __shfl_xor_sync(0xffffffffu, s, m);
        __shared__ float ws[8];
        if ((t & 31) == 0) ws[t >> 5] = s;
        __syncthreads();
        __shared__ float inv;
        if (t == 0) {
            float tot = 0.f;
            #pragma unroll
            for (int i = 0; i < 8; i++) tot += ws[i];
            inv = 1.0f / fmaxf(sqrtf(tot), 1e-12f);
        }
        __syncthreads();
        g_xbf[b * D_SZ + t] = __float2bfloat16(SCALE * v * inv);
    }
}

// ---------------- kernel 2: HMMA GEMM + exp-sum epilogue ----------------
// grid (4, 782): x = batch block (fast -> 4 CTAs of one class chunk launch
// adjacently and share the W tile in L2), y = class chunk.
__global__ void __launch_bounds__(256, 2)
gemm_lse_kernel() {
    extern __shared__ __align__(1024) char smem[];
    const uint32_t sb = smem_u32(smem);
    const int tid = threadIdx.x, lane = tid & 31, wid = tid >> 5;
    const int wm = wid >> 2, wn = wid & 3;            // warp grid 2 x 4
    const int chunk = blockIdx.y, c0 = chunk * 128, b0 = blockIdx.x * 128;

    // ---- cp.async producer indexing (swizzled 16B chunks) ----
    const int ldRow = tid >> 2, ldC16 = tid & 3;
    const uint32_t swzOff = (uint32_t)ldRow * 64 +
                            ((uint32_t)(ldC16 ^ ((ldRow >> 1) & 3)) << 4);
    const __nv_bfloat16* gA = g_xbf + (size_t)(b0 + ldRow) * D_SZ + ldC16 * 8;
    const __nv_bfloat16* gB = g_wbf + (size_t)(c0 + ldRow) * D_SZ + ldC16 * 8;

    auto load_stage = [&](int kt) {
        uint32_t abase = sb + (kt & 3) * STAGE_BYTES;
        uint32_t bbase = abase + 8192;
        const __nv_bfloat16* a = gA + kt * 32;
        const __nv_bfloat16* b = gB + kt * 32;
        CP_ASYNC16(abase + swzOff,        a);
        CP_ASYNC16(abase + swzOff + 4096, a + (size_t)64 * D_SZ);
        CP_ASYNC16(bbase + swzOff,        b);
        CP_ASYNC16(bbase + swzOff + 4096, b + (size_t)64 * D_SZ);
        CP_COMMIT();
    };

    // ---- ldmatrix consumer indexing ----
    const int rA = wm * 64 + (lane & 15);
    const uint32_t aoff = (uint32_t)rA * 64;
    const int saN = (rA >> 1) & 3;
    const int cA = lane >> 4;
    const int rB = wn * 32 + ((lane >> 4) << 3) + (lane & 7);
    const uint32_t boff = (uint32_t)rB * 64;
    const int sbN = (rB >> 1) & 3;
    const int cB = (lane >> 3) & 1;

    float acc[4][4][4];
    #pragma unroll
    for (int i = 0; i < 4; i++)
        #pragma unroll
        for (int j = 0; j < 4; j++)
            #pragma unroll
            for (int e = 0; e < 4; e++) acc[i][j][e] = 0.f;

    auto compute_stage = [&](int st) {
        uint32_t aBase = sb + st * STAGE_BYTES;
        uint32_t bBase = aBase + 8192;
        #pragma unroll
        for (int s = 0; s < 2; s++) {                 // two k16 steps per BK=32
            uint32_t a_[4][4], b_[2][4];
            #pragma unroll
            for (int mt = 0; mt < 4; mt++) {
                uint32_t ad = aBase + aoff + mt * 1024 +
                              ((uint32_t)((s * 2 + cA) ^ saN) << 4);
                LDSM_X4(a_[mt][0], a_[mt][1], a_[mt][2], a_[mt][3], ad);
            }
            #pragma unroll
            for (int jp = 0; jp < 2; jp++) {
                uint32_t bd = bBase + boff + jp * 1024 +
                              ((uint32_t)((s * 2 + cB) ^ sbN) << 4);
                LDSM_X4(b_[jp][0], b_[jp][1], b_[jp][2], b_[jp][3], bd);
            }
            #pragma unroll
            for (int mt = 0; mt < 4; mt++)
                #pragma unroll
                for (int nt = 0; nt < 4; nt++) {
                    int jp = nt >> 1, hb = (nt & 1) * 2;
                    MMA_BF16(acc[mt][nt][0], acc[mt][nt][1], acc[mt][nt][2], acc[mt][nt][3],
                             a_[mt][0], a_[mt][1], a_[mt][2], a_[mt][3],
                             b_[jp][hb], b_[jp][hb + 1]);
                }
        }
    };

    // ---- pipeline: 8 K-stages, 4 buffers, 3 in flight, one barrier per stage ----
    load_stage(0); load_stage(1); load_stage(2);
    #pragma unroll 1
    for (int kt = 0; kt < 5; kt++) {
        CP_WAIT(2); __syncthreads();
        compute_stage(kt & 3);
        load_stage(kt + 3);
    }
    CP_WAIT(2); __syncthreads(); compute_stage(1);    // stage 5
    CP_WAIT(1); __syncthreads(); compute_stage(2);    // stage 6
    CP_WAIT(0); __syncthreads(); compute_stage(3);    // stage 7

    // ---- epilogue: per-row sum of exp(v - SHIFT) ----
    const bool edge = (c0 + 128 > C_SZ);
    float es[4][2];
    #pragma unroll
    for (int mt = 0; mt < 4; mt++) { es[mt][0] = 0.f; es[mt][1] = 0.f; }
    #pragma unroll
    for (int mt = 0; mt < 4; mt++)
        #pragma unroll
        for (int nt = 0; nt < 4; nt++) {
            int cgb = c0 + wn * 32 + nt * 8 + (lane & 3) * 2;
            #pragma unroll
            for (int h = 0; h < 2; h++)
                #pragma unroll
                for (int e = 0; e < 2; e++) {
                    float t = __expf(acc[mt][nt][h * 2 + e] - SHIFT);
                    if (edge && (cgb + e >= C_SZ)) t = 0.f;
                    es[mt][h] += t;
                }
        }
    #pragma unroll
    for (int m = 1; m <= 2; m <<= 1)
        #pragma unroll
        for (int mt = 0; mt < 4; mt++) {
            es[mt][0] += __shfl_xor_sync(0xffffffffu, es[mt][0], m);
            es[mt][1] += __shfl_xor_sync(0xffffffffu, es[mt][1], m);
        }

    float* rbuf = (float*)(smem + RBUF_OFF);          // disjoint from stage buffers
    if ((lane & 3) == 0) {
        int rl = lane >> 2;
        #pragma unroll
        for (int mt = 0; mt < 4; mt++) {
            rbuf[(wm * 4 + wn) * 64 + mt * 16 + rl]     = es[mt][0];
            rbuf[(wm * 4 + wn) * 64 + mt * 16 + 8 + rl] = es[mt][1];
        }
    }
    __syncthreads();
    if (tid < 128) {
        int wmx = tid >> 6, rl = tid & 63;
        float s = rbuf[(wmx * 4 + 0) * 64 + rl] + rbuf[(wmx * 4 + 1) * 64 + rl]
                + rbuf[(wmx * 4 + 2) * 64 + rl] + rbuf[(wmx * 4 + 3) * 64 + rl];
        g_psum[(size_t)(b0 + tid) * NCHB + chunk] = s;
    }
}

// ---------------- kernel 3: per-row specials + LSE merge + loss ----------------
// 512 blocks x 256 threads. Warps 0-3 compute the 4 special dot products,
// all threads sum the row's 782 partials, thread 0 applies scatter corrections.
__global__ void row_kernel(const float* __restrict__ lamp,
                           const int* __restrict__ t1, const int* __restrict__ p1,
                           const int* __restrict__ t2, const int* __restrict__ p2) {
    int b = blockIdx.x;
    int tid = threadIdx.x, wid = tid >> 5, lane = tid & 31;

    __shared__ float sv[4], svraw[4];
    __shared__ int   sidx[4];
    __shared__ float ss[256];

    int i0 = t1[b], i1 = p1[b], i2 = t2[b], i3 = p2[b];

    if (wid < 4) {
        int qi = (wid == 0) ? i0 : (wid == 1) ? i1 : (wid == 2) ? i2 : i3;
        const uint4* xr = (const uint4*)(g_xbf + (size_t)b * D_SZ);
        const uint4* wr = (const uint4*)(g_wbf + (size_t)qi * D_SZ);
        uint4 xv = xr[lane], wv = wr[lane];
        float s = 0.f;
        const uint32_t* xu = (const uint32_t*)&xv;
        const uint32_t* wu = (const uint32_t*)&wv;
        #pragma unroll
        for (int i = 0; i < 4; i++) {
            float2 xf = __bfloat1622float2(*(const __nv_bfloat162*)&xu[i]);
            float2 wf = __bfloat1622float2(*(const __nv_bfloat162*)&wu[i]);
            s += xf.x * wf.x + xf.y * wf.y;
        }
        #pragma unroll
        for (int m = 16; m; m >>= 1) s += __shfl_xor_sync(0xffffffffu, s, m);
        if (lane == 0) {
            float raw = s;                               // S * cos (bf16 ops)
            float val = raw;
            if (qi == i0) val = raw - SCALE * MARGIN;    // pre-scale scatter
            if (qi == i1) val = raw / SCALE - MARGIN;    // post-scale scatters
            if (qi == i2) val = raw / SCALE - MARGIN;
            if (qi == i3) val = raw / SCALE - MARGIN;    // last write wins
            svraw[wid] = raw;
            sv[wid] = val;
            sidx[wid] = qi;
        }
    }

    float s = 0.f;
    for (int i = tid; i < NCHB; i += 256) s += g_psum[(size_t)b * NCHB + i];
    ss[tid] = s;
    __syncthreads();
    for (int st = 128; st; st >>= 1) {
        if (tid < st) ss[tid] += ss[tid + st];
        __syncthreads();
    }

    if (tid == 0) {
        float S0 = ss[0];
        #pragma unroll
        for (int q = 0; q < 3; q++) {
            bool last = true;
            #pragma unroll
            for (int r = q + 1; r < 4; r++) if (sidx[r] == sidx[q]) last = false;
            if (last) S0 += __expf(sv[q] - SHIFT) - __expf(svraw[q] - SHIFT);
        }
        S0 += __expf(sv[3] - SHIFT) - __expf(svraw[3] - SHIFT);
        float lz = SHIFT + logf(S0);
        float lam = *lamp;
        g_loss[b] = lam * (0.2f * (lz - sv[0]) + 0.8f * (lz - sv[1]))
                  + (1.f - lam) * (0.2f * (lz - sv[2]) + 0.8f * (lz - sv[3]));
    }
}

// ---------------- kernel 4: final reduction ----------------
__global__ void final_kernel(float* __restrict__ out) {
    int b = threadIdx.x;     // 512
    __shared__ float red[512];
    red[b] = g_loss[b];
    __syncthreads();
    for (int st = 256; st; st >>= 1) {
        if (b < st) red[b] += red[b + st];
        __syncthreads();
    }
    if (b == 0) out[0] = red[0] / (float)B_SZ;
}

// ---------------- host launch ----------------
extern "C" void kernel_launch(void* const* d_in, const int* in_sizes, int n_in,
                              void* d_out, int out_size) {
    const float* x   = (const float*)d_in[0];
    const float* w   = (const float*)d_in[1];
    const float* lam = (const float*)d_in[2];
    const int* t1    = (const int*)d_in[3];
    const int* p1    = (const int*)d_in[4];
    const int* t2    = (const int*)d_in[5];
    const int* p2    = (const int*)d_in[6];
    float* out = (float*)d_out;

    static bool attr_set = false;
    if (!attr_set) {
        cudaFuncSetAttribute(gemm_lse_kernel,
                             cudaFuncAttributeMaxDynamicSharedMemorySize, GEMM_SMEM);
        attr_set = true;
    }

    prep_kernel<<<WCONV_BLOCKS + B_SZ, 256>>>(w, x);
    gemm_lse_kernel<<<dim3(4, NCHB), 256, GEMM_SMEM>>>();
    row_kernel<<<B_SZ, 256>>>(lam, t1, p1, t2, p2);
    final_kernel<<<1, 512>>>(out);
}